// round 5
// baseline (speedup 1.0000x reference)
#include <cuda_runtime.h>
#include <cuda_fp16.h>
#include <stdint.h>

typedef uint32_t u32;
typedef unsigned long long u64t;

// Problem constants
#define Nb   4
#define VQn  4096
#define VKn  4096
#define Cdim 128
#define Hdim 64

#define LOG2E 1.44269504f

// ---------------- scratch (static device globals; fp16) ---------------------
__device__ __align__(128) __half g_q[(size_t)Nb * VQn * Hdim];   // pre-scaled by 0.125*log2e
__device__ __align__(128) __half g_k[(size_t)Nb * VKn * Hdim];
__device__ __align__(128) __half g_vt[(size_t)Nb * Cdim * VKn];  // V^T[n][dv][key]

// ---------------- helpers ----------------------------------------------------
__device__ __forceinline__ u32 s2u(const void* p) {
    u32 a;
    asm("{ .reg .u64 t; cvta.to.shared.u64 t, %1; cvt.u32.u64 %0, t; }"
        : "=r"(a) : "l"(p));
    return a;
}
__device__ __forceinline__ void cp16(u32 dst, const void* src) {
    asm volatile("cp.async.cg.shared.global [%0], [%1], 16;"
                 :: "r"(dst), "l"(src) : "memory");
}
__device__ __forceinline__ void cp_commit() {
    asm volatile("cp.async.commit_group;" ::: "memory");
}
template <int N>
__device__ __forceinline__ void cp_wait() {
    asm volatile("cp.async.wait_group %0;" :: "n"(N) : "memory");
}
__device__ __forceinline__ u32 pk(float lo, float hi) {
    u32 d;
    asm("cvt.rn.f16x2.f32 %0, %1, %2;" : "=r"(d) : "f"(hi), "f"(lo));
    return d;
}
__device__ __forceinline__ void ldsm4(u32& r0, u32& r1, u32& r2, u32& r3, u32 a) {
    asm volatile("ldmatrix.sync.aligned.m8n8.x4.shared.b16 {%0,%1,%2,%3}, [%4];"
                 : "=r"(r0), "=r"(r1), "=r"(r2), "=r"(r3) : "r"(a));
}
__device__ __forceinline__ void mma16816(float* d, u32 a0, u32 a1, u32 a2, u32 a3,
                                         u32 b0, u32 b1) {
    asm volatile(
        "mma.sync.aligned.m16n8k16.row.col.f32.f16.f16.f32 "
        "{%0,%1,%2,%3}, {%4,%5,%6,%7}, {%8,%9}, {%0,%1,%2,%3};"
        : "+f"(d[0]), "+f"(d[1]), "+f"(d[2]), "+f"(d[3])
        : "r"(a0), "r"(a1), "r"(a2), "r"(a3), "r"(b0), "r"(b1));
}
// input already in log2 domain (Q pre-scaled by log2e)
__device__ __forceinline__ float fexp2(float s) {
    float r;
    asm("ex2.approx.f32 %0, %1;" : "=f"(r) : "f"(fminf(s, 20.f)));
    return r;
}
__device__ __forceinline__ u64t pack2(float x, float y) {
    u64t r; asm("mov.b64 %0, {%1, %2};" : "=l"(r) : "f"(x), "f"(y)); return r;
}
__device__ __forceinline__ u64t dup2(float x) { return pack2(x, x); }
__device__ __forceinline__ void fma2(u64t& d, u64t a, u64t b) {
    asm("fma.rn.f32x2 %0, %1, %2, %0;" : "+l"(d) : "l"(a), "l"(b));
}
__device__ __forceinline__ float2 unpack2(u64t v) {
    float2 r; asm("mov.b64 {%0, %1}, %2;" : "=f"(r.x), "=f"(r.y) : "l"(v)); return r;
}

// ---------------- merged projection kernel (fp32x2 math, fp16 out) -----------
__device__ __forceinline__ void proj_qk_body(
    const float* __restrict__ A, const float* __restrict__ W,
    __half* __restrict__ o, float scale, float* pool) {
    constexpr int KC = 32;
    constexpr int H = 64;
    float (*As)[128 + 4] = (float(*)[128 + 4])pool;
    float (*Ws)[H] = (float(*)[H])(pool + KC * (128 + 4));
    const int tid = threadIdx.x;
    const int tx = tid & 15;
    const int ty = tid >> 4;
    const int r0 = blockIdx.x * 128;

    u64t acc2[8][2];
#pragma unroll
    for (int i = 0; i < 8; i++) { acc2[i][0] = 0; acc2[i][1] = 0; }

    for (int c0 = 0; c0 < Cdim; c0 += KC) {
        __syncthreads();
#pragma unroll
        for (int it = 0; it < 4; it++) {
            int i = tid + it * 256;
            int r = i >> 3, c4 = i & 7;
            float4 v = *(const float4*)(A + (size_t)(r0 + r) * Cdim + c0 + c4 * 4);
            As[c4 * 4 + 0][r] = v.x; As[c4 * 4 + 1][r] = v.y;
            As[c4 * 4 + 2][r] = v.z; As[c4 * 4 + 3][r] = v.w;
        }
#pragma unroll
        for (int it = 0; it < 2; it++) {
            int i = tid + it * 256;
            int r = i / 16, c4 = i % 16;
            *(float4*)&Ws[r][c4 * 4] = *(const float4*)(W + (size_t)(c0 + r) * H + c4 * 4);
        }
        __syncthreads();
#pragma unroll
        for (int c = 0; c < KC; c++) {
            float a[8];
            *(float4*)&a[0] = *(const float4*)&As[c][ty * 8];
            *(float4*)&a[4] = *(const float4*)&As[c][ty * 8 + 4];
            float4 w = *(const float4*)&Ws[c][tx * 4];
            u64t w2[2] = { pack2(w.x, w.y), pack2(w.z, w.w) };
#pragma unroll
            for (int i = 0; i < 8; i++) {
                u64t a2 = dup2(a[i]);
                fma2(acc2[i][0], a2, w2[0]);
                fma2(acc2[i][1], a2, w2[1]);
            }
        }
    }
#pragma unroll
    for (int i = 0; i < 8; i++) {
        size_t row = (size_t)(r0 + ty * 8 + i);
        float2 c01 = unpack2(acc2[i][0]);
        float2 c23 = unpack2(acc2[i][1]);
        u32 w0 = pk(c01.x * scale, c01.y * scale);
        u32 w1 = pk(c23.x * scale, c23.y * scale);
        *(uint2*)(o + row * 64 + tx * 4) = make_uint2(w0, w1);
    }
}

__device__ __forceinline__ void proj_v_body(
    const float* __restrict__ A, const float* __restrict__ W,
    __half* __restrict__ ovt, float* pool) {
    constexpr int KC = 32;
    constexpr int H = 128;
    float (*As)[128 + 4] = (float(*)[128 + 4])pool;
    float (*Ws)[H] = (float(*)[H])(pool + KC * (128 + 4));
    const int tid = threadIdx.x;
    const int tx = tid & 15;
    const int ty = tid >> 4;
    const int r0 = blockIdx.x * 128;

    u64t acc2[4][8];
#pragma unroll
    for (int i = 0; i < 4; i++)
#pragma unroll
        for (int j = 0; j < 8; j++) acc2[i][j] = 0;

    for (int c0 = 0; c0 < Cdim; c0 += KC) {
        __syncthreads();
#pragma unroll
        for (int it = 0; it < 4; it++) {
            int i = tid + it * 256;
            int r = i >> 3, c4 = i & 7;
            float4 v = *(const float4*)(A + (size_t)(r0 + r) * Cdim + c0 + c4 * 4);
            As[c4 * 4 + 0][r] = v.x; As[c4 * 4 + 1][r] = v.y;
            As[c4 * 4 + 2][r] = v.z; As[c4 * 4 + 3][r] = v.w;
        }
#pragma unroll
        for (int it = 0; it < 4; it++) {
            int i = tid + it * 256;
            int r = i / 32, c4 = i % 32;
            *(float4*)&Ws[r][c4 * 4] = *(const float4*)(W + (size_t)(c0 + r) * H + c4 * 4);
        }
        __syncthreads();
#pragma unroll
        for (int c = 0; c < KC; c++) {
            float a[8];
            *(float4*)&a[0] = *(const float4*)&As[c][ty * 8];
            *(float4*)&a[4] = *(const float4*)&As[c][ty * 8 + 4];
            float w[8];
            *(float4*)&w[0] = *(const float4*)&Ws[c][tx * 8];
            *(float4*)&w[4] = *(const float4*)&Ws[c][tx * 8 + 4];
            u64t a2[4] = { pack2(a[0], a[1]), pack2(a[2], a[3]),
                           pack2(a[4], a[5]), pack2(a[6], a[7]) };
#pragma unroll
            for (int j = 0; j < 8; j++) {
                u64t w2 = dup2(w[j]);
#pragma unroll
                for (int rp = 0; rp < 4; rp++)
                    fma2(acc2[rp][j], a2[rp], w2);
            }
        }
    }
    const int n = r0 >> 12;
    const int key0 = (r0 & 4095) + ty * 8;
#pragma unroll
    for (int j = 0; j < 8; j++) {
        int dv = tx * 8 + j;
        u32 w[4];
#pragma unroll
        for (int q = 0; q < 4; q++) {
            float2 f = unpack2(acc2[q][j]);
            w[q] = pk(f.x, f.y);
        }
        size_t base = ((size_t)n * 128 + dv) * 4096 + key0;
        *(uint4*)(ovt + base) = make_uint4(w[0], w[1], w[2], w[3]);
    }
}

__global__ __launch_bounds__(256)
void proj_all(const float* __restrict__ x, const float* __restrict__ y,
              const float* __restrict__ Wq, const float* __restrict__ Wk,
              const float* __restrict__ Wv,
              __half* __restrict__ q, __half* __restrict__ k,
              __half* __restrict__ vt) {
    __shared__ float pool[32 * (128 + 4) + 32 * 128];
    const int task = blockIdx.y;
    if (task == 0)      proj_qk_body(x, Wq, q, 0.125f * LOG2E, pool);
    else if (task == 1) proj_qk_body(y, Wk, k, 1.0f, pool);
    else                proj_v_body(y, Wv, vt, pool);
}

// ---------------- flash attention: 512 threads, key-split warps ---------------
#define BM  128
#define BN  64
#define NT  (VKn / BN)    // 64
#define NTHREADS 512

// 3-stage smem ring (bytes)
#define SM_Q       0
#define SM_K3(s)   (16384 + (s) * 8192)
#define SM_V3(s)   (40960 + (s) * 16384)
#define SMEM_TOTAL 90112
// epilogue overlays (after main loop): O partial 128x128 f32 = 64KB, l 128 f32
#define SM_LRED    65536

__device__ __forceinline__ void load_kv(u32 sb, int stage, const char* kB,
                                        const char* vB, int kt, int tid) {
    const size_t krow = (size_t)kt * BN;
    {
        int i = tid;              // 512 chunks of 16B = 8KB (K tile)
        u32 r = i >> 3, c = i & 7;
        cp16(sb + SM_K3(stage) + r * 128 + ((c ^ (r & 7)) << 4),
             kB + (krow + r) * 128 + c * 16);
    }
    const u32 vdst = sb + SM_V3(stage);
#pragma unroll
    for (int it = 0; it < 2; it++) {  // 1024 chunks = 16KB (V^T tile)
        int i = tid + it * NTHREADS;
        u32 r = i >> 3, c = i & 7;
        cp16(vdst + r * 128 + ((c ^ (r & 7)) << 4),
             vB + (size_t)r * 8192 + krow * 2 + c * 16);
    }
    cp_commit();
}

__global__ __launch_bounds__(NTHREADS, 1)
void flash_mma(const __half* __restrict__ Q, const __half* __restrict__ K,
               const __half* __restrict__ VT, float* __restrict__ out) {
    extern __shared__ char smx[];
    const u32 sb = s2u(smx);
    const int tid  = threadIdx.x;
    const int wid  = tid >> 5;
    const int lane = tid & 31;
    const int g    = wid & 7;    // row group: rows [16g, 16g+16)
    const int kh   = wid >> 3;   // key half: keys [32kh, 32kh+32) of each tile
    const int n  = blockIdx.y;
    const int q0 = blockIdx.x * BM;

    const char* qB = (const char*)(Q + ((size_t)n * VQn + q0) * Hdim);
    const char* kB = (const char*)(K + (size_t)n * VKn * Hdim);
    const char* vB = (const char*)(VT + (size_t)n * Cdim * VKn);

    // ---- prologue: Q + K0/V0 (group A), K1/V1 (group B) ----
#pragma unroll
    for (int it = 0; it < 2; it++) {
        int i = tid + it * NTHREADS;
        u32 r = i >> 3, c = i & 7;
        cp16(sb + SM_Q + r * 128 + ((c ^ (r & 7)) << 4), qB + r * 128 + c * 16);
    }
    load_kv(sb, 0, kB, vB, 0, tid);
    load_kv(sb, 1, kB, vB, 1, tid);
    cp_wait<1>();
    __syncthreads();

    // ldmatrix lane patterns
    const u32 l7 = lane & 7;
    const u32 rowA = (l7 + 8 * ((lane >> 3) & 1)) * 128;
    const u32 rowB = (l7 + 8 * ((lane >> 4) & 1)) * 128;
    const u32 bitA = (lane >> 4) & 1;
    const u32 bitB = (lane >> 3) & 1;
    u32 cswzA[4], cswzK[4], cswzV[2];
#pragma unroll
    for (int kk = 0; kk < 4; kk++) {
        cswzA[kk] = (((2 * kk + bitA) ^ l7) << 4);
        cswzK[kk] = (((2 * kk + bitB) ^ l7) << 4);
    }
#pragma unroll
    for (int kk = 0; kk < 2; kk++)
        cswzV[kk] = ((((u32)(4 * kh) + 2 * kk + bitB) ^ l7) << 4);

    // Q fragments (16 rows x 64 k), register-resident
    u32 qf[4][4];
    {
        const u32 qbase = sb + SM_Q + (u32)(g * 16) * 128 + rowA;
#pragma unroll
        for (int kk = 0; kk < 4; kk++)
            ldsm4(qf[kk][0], qf[kk][1], qf[kk][2], qf[kk][3], qbase + cswzA[kk]);
    }

    float oacc[16][4];
#pragma unroll
    for (int v = 0; v < 16; v++)
#pragma unroll
        for (int c = 0; c < 4; c++) oacc[v][c] = 0.f;
    float l0 = 0.f, l1 = 0.f;

    int st0 = 0, st1 = 1, st2 = 2;
    const u32 koff = (u32)(kh * 32) * 128;   // this warp's key-half in K stage

    for (int kt = 0; kt < NT; kt++) {
        if (kt + 1 < NT) cp_wait<1>(); else cp_wait<0>();
        __syncthreads();
        if (kt + 2 < NT) load_kv(sb, st2, kB, vB, kt + 2, tid);

        // ---- S(16x32) = Q(16x64) @ K_half^T ----
        float sacc[4][4];
#pragma unroll
        for (int j = 0; j < 4; j++)
#pragma unroll
            for (int c = 0; c < 4; c++) sacc[j][c] = 0.f;
        const u32 kbase = sb + SM_K3(st0) + koff + rowB;
#pragma unroll
        for (int jp = 0; jp < 2; jp++)
#pragma unroll
            for (int kk = 0; kk < 4; kk++) {
                u32 b0, b1, b2, b3;
                ldsm4(b0, b1, b2, b3, kbase + jp * 2048 + cswzK[kk]);
                mma16816(sacc[2 * jp],     qf[kk][0], qf[kk][1], qf[kk][2], qf[kk][3], b0, b1);
                mma16816(sacc[2 * jp + 1], qf[kk][0], qf[kk][1], qf[kk][2], qf[kk][3], b2, b3);
            }

        // ---- softmax partial (16 exps) ----
        uint2 pa[4];
#pragma unroll
        for (int j = 0; j < 4; j++) {
            float p0 = fexp2(sacc[j][0]);
            float p1 = fexp2(sacc[j][1]);
            float p2 = fexp2(sacc[j][2]);
            float p3 = fexp2(sacc[j][3]);
            l0 += p0 + p1;
            l1 += p2 + p3;
            pa[j].x = pk(p0, p1);
            pa[j].y = pk(p2, p3);
        }

        // ---- O(16x128) += P(16x32) @ V_half(32x128) ----
        const u32 vbase = sb + SM_V3(st0) + rowB;
#pragma unroll
        for (int nvp = 0; nvp < 8; nvp++)
#pragma unroll
            for (int kk = 0; kk < 2; kk++) {
                u32 b0, b1, b2, b3;
                ldsm4(b0, b1, b2, b3, vbase + nvp * 2048 + cswzV[kk]);
                mma16816(oacc[2 * nvp],
                         pa[2 * kk].x, pa[2 * kk].y, pa[2 * kk + 1].x, pa[2 * kk + 1].y, b0, b1);
                mma16816(oacc[2 * nvp + 1],
                         pa[2 * kk].x, pa[2 * kk].y, pa[2 * kk + 1].x, pa[2 * kk + 1].y, b2, b3);
            }

        int t = st0; st0 = st1; st1 = st2; st2 = t;
    }

    // ---- epilogue: cross-key-half reduce through smem, then normalize ----
#pragma unroll
    for (int d = 1; d < 4; d <<= 1) {
        l0 += __shfl_xor_sync(0xffffffffu, l0, d);
        l1 += __shfl_xor_sync(0xffffffffu, l1, d);
    }
    const int r0l = g * 16 + (lane >> 2);    // local row (0..127)
    const int cl  = 2 * (lane & 3);          // local col base within 8-col tile
    float* Ored = (float*)smx;
    float* lred = (float*)(smx + SM_LRED);

    __syncthreads();   // everyone done with smem ring
    if (kh == 1) {
#pragma unroll
        for (int v = 0; v < 16; v++) {
            *(float2*)&Ored[(size_t)r0l * 128 + v * 8 + cl] =
                make_float2(oacc[v][0], oacc[v][1]);
            *(float2*)&Ored[(size_t)(r0l + 8) * 128 + v * 8 + cl] =
                make_float2(oacc[v][2], oacc[v][3]);
        }
        if ((lane & 3) == 0) { lred[r0l] = l0; lred[r0l + 8] = l1; }
    }
    __syncthreads();
    if (kh == 0) {
        const float inv0 = 1.f / (l0 + lred[r0l]);
        const float inv1 = 1.f / (l1 + lred[r0l + 8]);
        float* o0 = out + ((size_t)n * VQn + q0 + r0l) * Cdim + cl;
        float* o1 = o0 + 8 * Cdim;
#pragma unroll
        for (int v = 0; v < 16; v++) {
            float2 a = *(const float2*)&Ored[(size_t)r0l * 128 + v * 8 + cl];
            float2 b = *(const float2*)&Ored[(size_t)(r0l + 8) * 128 + v * 8 + cl];
            *(float2*)(o0 + v * 8) = make_float2((oacc[v][0] + a.x) * inv0,
                                                 (oacc[v][1] + a.y) * inv0);
            *(float2*)(o1 + v * 8) = make_float2((oacc[v][2] + b.x) * inv1,
                                                 (oacc[v][3] + b.y) * inv1);
        }
    }
}

// ---------------- launch ------------------------------------------------------
extern "C" void kernel_launch(void* const* d_in, const int* in_sizes, int n_in,
                              void* d_out, int out_size) {
    (void)in_sizes; (void)n_in; (void)out_size;
    const float* x  = (const float*)d_in[0];
    const float* y  = (const float*)d_in[1];
    const float* Wq = (const float*)d_in[2];
    const float* Wk = (const float*)d_in[3];
    const float* Wv = (const float*)d_in[4];
    float* out = (float*)d_out;

    __half *qp, *kp, *vtp;
    cudaGetSymbolAddress((void**)&qp, g_q);
    cudaGetSymbolAddress((void**)&kp, g_k);
    cudaGetSymbolAddress((void**)&vtp, g_vt);

    cudaFuncSetAttribute(flash_mma,
                         cudaFuncAttributeMaxDynamicSharedMemorySize, SMEM_TOTAL);

    dim3 pgrid(Nb * VQn / 128, 3);
    proj_all<<<pgrid, 256>>>(x, y, Wq, Wk, Wv, qp, kp, vtp);

    dim3 grid(VQn / BM, Nb);
    flash_mma<<<grid, NTHREADS, SMEM_TOTAL>>>(qp, kp, vtp, out);
}

// round 6
// speedup vs baseline: 1.0369x; 1.0369x over previous
#include <cuda_runtime.h>
#include <cuda_fp16.h>
#include <stdint.h>

typedef uint32_t u32;
typedef unsigned long long u64t;

// Problem constants
#define Nb   4
#define VQn  4096
#define VKn  4096
#define Cdim 128
#define Hdim 64

#define LOG2E 1.44269504f

// ---------------- scratch (static device globals; fp16) ---------------------
__device__ __align__(128) __half g_q[(size_t)Nb * VQn * Hdim];   // pre-scaled by 0.125*log2e
__device__ __align__(128) __half g_k[(size_t)Nb * VKn * Hdim];
__device__ __align__(128) __half g_vt[(size_t)Nb * Cdim * VKn];  // V^T[n][dv][key]

// ---------------- helpers ----------------------------------------------------
__device__ __forceinline__ u32 s2u(const void* p) {
    u32 a;
    asm("{ .reg .u64 t; cvta.to.shared.u64 t, %1; cvt.u32.u64 %0, t; }"
        : "=r"(a) : "l"(p));
    return a;
}
__device__ __forceinline__ void cp16(u32 dst, const void* src) {
    asm volatile("cp.async.cg.shared.global [%0], [%1], 16;"
                 :: "r"(dst), "l"(src) : "memory");
}
__device__ __forceinline__ void cp_commit() {
    asm volatile("cp.async.commit_group;" ::: "memory");
}
template <int N>
__device__ __forceinline__ void cp_wait() {
    asm volatile("cp.async.wait_group %0;" :: "n"(N) : "memory");
}
__device__ __forceinline__ u32 pk(float lo, float hi) {
    u32 d;
    asm("cvt.rn.f16x2.f32 %0, %1, %2;" : "=r"(d) : "f"(hi), "f"(lo));
    return d;
}
__device__ __forceinline__ void ldsm4(u32& r0, u32& r1, u32& r2, u32& r3, u32 a) {
    asm volatile("ldmatrix.sync.aligned.m8n8.x4.shared.b16 {%0,%1,%2,%3}, [%4];"
                 : "=r"(r0), "=r"(r1), "=r"(r2), "=r"(r3) : "r"(a));
}
__device__ __forceinline__ void mma16816(float* d, u32 a0, u32 a1, u32 a2, u32 a3,
                                         u32 b0, u32 b1) {
    asm volatile(
        "mma.sync.aligned.m16n8k16.row.col.f32.f16.f16.f32 "
        "{%0,%1,%2,%3}, {%4,%5,%6,%7}, {%8,%9}, {%0,%1,%2,%3};"
        : "+f"(d[0]), "+f"(d[1]), "+f"(d[2]), "+f"(d[3])
        : "r"(a0), "r"(a1), "r"(a2), "r"(a3), "r"(b0), "r"(b1));
}
// input already in log2 domain (Q pre-scaled by log2e)
__device__ __forceinline__ float fexp2(float s) {
    float r;
    asm("ex2.approx.f32 %0, %1;" : "=f"(r) : "f"(fminf(s, 20.f)));
    return r;
}
__device__ __forceinline__ u64t pack2(float x, float y) {
    u64t r; asm("mov.b64 %0, {%1, %2};" : "=l"(r) : "f"(x), "f"(y)); return r;
}
__device__ __forceinline__ u64t dup2(float x) { return pack2(x, x); }
__device__ __forceinline__ void fma2(u64t& d, u64t a, u64t b) {
    asm("fma.rn.f32x2 %0, %1, %2, %0;" : "+l"(d) : "l"(a), "l"(b));
}
__device__ __forceinline__ float2 unpack2(u64t v) {
    float2 r; asm("mov.b64 {%0, %1}, %2;" : "=f"(r.x), "=f"(r.y) : "l"(v)); return r;
}

// ---------------- merged projection kernel (fp32x2 math, fp16 out) -----------
__device__ __forceinline__ void proj_qk_body(
    const float* __restrict__ A, const float* __restrict__ W,
    __half* __restrict__ o, float scale, float* pool) {
    constexpr int KC = 32;
    constexpr int H = 64;
    float (*As)[128 + 4] = (float(*)[128 + 4])pool;
    float (*Ws)[H] = (float(*)[H])(pool + KC * (128 + 4));
    const int tid = threadIdx.x;
    const int tx = tid & 15;
    const int ty = tid >> 4;
    const int r0 = blockIdx.x * 128;

    u64t acc2[8][2];
#pragma unroll
    for (int i = 0; i < 8; i++) { acc2[i][0] = 0; acc2[i][1] = 0; }

    for (int c0 = 0; c0 < Cdim; c0 += KC) {
        __syncthreads();
#pragma unroll
        for (int it = 0; it < 4; it++) {
            int i = tid + it * 256;
            int r = i >> 3, c4 = i & 7;
            float4 v = *(const float4*)(A + (size_t)(r0 + r) * Cdim + c0 + c4 * 4);
            As[c4 * 4 + 0][r] = v.x; As[c4 * 4 + 1][r] = v.y;
            As[c4 * 4 + 2][r] = v.z; As[c4 * 4 + 3][r] = v.w;
        }
#pragma unroll
        for (int it = 0; it < 2; it++) {
            int i = tid + it * 256;
            int r = i / 16, c4 = i % 16;
            *(float4*)&Ws[r][c4 * 4] = *(const float4*)(W + (size_t)(c0 + r) * H + c4 * 4);
        }
        __syncthreads();
#pragma unroll
        for (int c = 0; c < KC; c++) {
            float a[8];
            *(float4*)&a[0] = *(const float4*)&As[c][ty * 8];
            *(float4*)&a[4] = *(const float4*)&As[c][ty * 8 + 4];
            float4 w = *(const float4*)&Ws[c][tx * 4];
            u64t w2[2] = { pack2(w.x, w.y), pack2(w.z, w.w) };
#pragma unroll
            for (int i = 0; i < 8; i++) {
                u64t a2 = dup2(a[i]);
                fma2(acc2[i][0], a2, w2[0]);
                fma2(acc2[i][1], a2, w2[1]);
            }
        }
    }
#pragma unroll
    for (int i = 0; i < 8; i++) {
        size_t row = (size_t)(r0 + ty * 8 + i);
        float2 c01 = unpack2(acc2[i][0]);
        float2 c23 = unpack2(acc2[i][1]);
        u32 w0 = pk(c01.x * scale, c01.y * scale);
        u32 w1 = pk(c23.x * scale, c23.y * scale);
        *(uint2*)(o + row * 64 + tx * 4) = make_uint2(w0, w1);
    }
}

__device__ __forceinline__ void proj_v_body(
    const float* __restrict__ A, const float* __restrict__ W,
    __half* __restrict__ ovt, float* pool) {
    constexpr int KC = 32;
    constexpr int H = 128;
    float (*As)[128 + 4] = (float(*)[128 + 4])pool;
    float (*Ws)[H] = (float(*)[H])(pool + KC * (128 + 4));
    const int tid = threadIdx.x;
    const int tx = tid & 15;
    const int ty = tid >> 4;
    const int r0 = blockIdx.x * 128;

    u64t acc2[4][8];
#pragma unroll
    for (int i = 0; i < 4; i++)
#pragma unroll
        for (int j = 0; j < 8; j++) acc2[i][j] = 0;

    for (int c0 = 0; c0 < Cdim; c0 += KC) {
        __syncthreads();
#pragma unroll
        for (int it = 0; it < 4; it++) {
            int i = tid + it * 256;
            int r = i >> 3, c4 = i & 7;
            float4 v = *(const float4*)(A + (size_t)(r0 + r) * Cdim + c0 + c4 * 4);
            As[c4 * 4 + 0][r] = v.x; As[c4 * 4 + 1][r] = v.y;
            As[c4 * 4 + 2][r] = v.z; As[c4 * 4 + 3][r] = v.w;
        }
#pragma unroll
        for (int it = 0; it < 4; it++) {
            int i = tid + it * 256;
            int r = i / 32, c4 = i % 32;
            *(float4*)&Ws[r][c4 * 4] = *(const float4*)(W + (size_t)(c0 + r) * H + c4 * 4);
        }
        __syncthreads();
#pragma unroll
        for (int c = 0; c < KC; c++) {
            float a[8];
            *(float4*)&a[0] = *(const float4*)&As[c][ty * 8];
            *(float4*)&a[4] = *(const float4*)&As[c][ty * 8 + 4];
            float w[8];
            *(float4*)&w[0] = *(const float4*)&Ws[c][tx * 8];
            *(float4*)&w[4] = *(const float4*)&Ws[c][tx * 8 + 4];
            u64t a2[4] = { pack2(a[0], a[1]), pack2(a[2], a[3]),
                           pack2(a[4], a[5]), pack2(a[6], a[7]) };
#pragma unroll
            for (int j = 0; j < 8; j++) {
                u64t w2 = dup2(w[j]);
#pragma unroll
                for (int rp = 0; rp < 4; rp++)
                    fma2(acc2[rp][j], a2[rp], w2);
            }
        }
    }
    const int n = r0 >> 12;
    const int key0 = (r0 & 4095) + ty * 8;
#pragma unroll
    for (int j = 0; j < 8; j++) {
        int dv = tx * 8 + j;
        u32 w[4];
#pragma unroll
        for (int q = 0; q < 4; q++) {
            float2 f = unpack2(acc2[q][j]);
            w[q] = pk(f.x, f.y);
        }
        size_t base = ((size_t)n * 128 + dv) * 4096 + key0;
        *(uint4*)(ovt + base) = make_uint4(w[0], w[1], w[2], w[3]);
    }
}

__global__ __launch_bounds__(256)
void proj_all(const float* __restrict__ x, const float* __restrict__ y,
              const float* __restrict__ Wq, const float* __restrict__ Wk,
              const float* __restrict__ Wv,
              __half* __restrict__ q, __half* __restrict__ k,
              __half* __restrict__ vt) {
    __shared__ float pool[32 * (128 + 4) + 32 * 128];
    const int task = blockIdx.y;
    if (task == 0)      proj_qk_body(x, Wq, q, 0.125f * LOG2E, pool);
    else if (task == 1) proj_qk_body(y, Wk, k, 1.0f, pool);
    else                proj_v_body(y, Wv, vt, pool);
}

// -------- flash attention: 512 thr, 2 warp-groups ping-pong on tiles ---------
#define BM  128
#define BN  64
#define NT  (VKn / BN)    // 64
#define NTHREADS 512

// smem layout (bytes): Q + 4 KV stages of 24KB (K 8KB + V 16KB)
#define SM_Q       0
#define SM_KS(s)   (16384 + (s) * 24576)
#define SM_VS(s)   (SM_KS(s) + 8192)
#define SMEM_TOTAL 114688
// epilogue overlay (after all compute): O partial 128x128 f32 + l[128]
#define SM_LRED    65536

// group loads: 256 threads of the group fill one 24KB stage
__device__ __forceinline__ void load_kv(u32 sb, int stage, const char* kB,
                                        const char* vB, int kt, int gtid) {
    const size_t krow = (size_t)kt * BN;
    const u32 kdst = sb + SM_KS(stage);
#pragma unroll
    for (int it = 0; it < 2; it++) {       // 512 x 16B = 8KB (K tile)
        int i = gtid + it * 256;
        u32 r = i >> 3, c = i & 7;
        cp16(kdst + r * 128 + ((c ^ (r & 7)) << 4), kB + (krow + r) * 128 + c * 16);
    }
    const u32 vdst = sb + SM_VS(stage);
#pragma unroll
    for (int it = 0; it < 4; it++) {       // 1024 x 16B = 16KB (V^T tile)
        int i = gtid + it * 256;
        u32 r = i >> 3, c = i & 7;
        cp16(vdst + r * 128 + ((c ^ (r & 7)) << 4),
             vB + (size_t)r * 8192 + krow * 2 + c * 16);
    }
    cp_commit();
}

__device__ __forceinline__ void gbar(int grp) {
    asm volatile("bar.sync %0, 256;" :: "r"(grp + 1) : "memory");
}

__global__ __launch_bounds__(NTHREADS, 1)
void flash_mma(const __half* __restrict__ Q, const __half* __restrict__ K,
               const __half* __restrict__ VT, float* __restrict__ out) {
    extern __shared__ char smx[];
    const u32 sb = s2u(smx);
    const int tid  = threadIdx.x;
    const int wid  = tid >> 5;
    const int lane = tid & 31;
    const int grp  = wid >> 3;     // tile-parity group: 0 = even tiles, 1 = odd
    const int wg   = wid & 7;      // row group within group: rows [16wg,16wg+16)
    const int gtid = tid & 255;    // index within group
    const int n  = blockIdx.y;
    const int q0 = blockIdx.x * BM;

    const char* qB = (const char*)(Q + ((size_t)n * VQn + q0) * Hdim);
    const char* kB = (const char*)(K + (size_t)n * VKn * Hdim);
    const char* vB = (const char*)(VT + (size_t)n * Cdim * VKn);

    // ---- prologue: Q (all threads), then group's first two tiles ----
#pragma unroll
    for (int it = 0; it < 2; it++) {
        int i = tid + it * NTHREADS;
        u32 r = i >> 3, c = i & 7;
        cp16(sb + SM_Q + r * 128 + ((c ^ (r & 7)) << 4), qB + r * 128 + c * 16);
    }
    cp_commit();                                // commit: Q
    load_kv(sb, grp,     kB, vB, grp,     gtid);    // commit: tile grp
    load_kv(sb, grp + 2, kB, vB, grp + 2, gtid);    // commit: tile grp+2
    cp_wait<1>();       // own Q + first-tile cps done
    __syncthreads();    // Q visible to all (ldsm reads others' writes)

    // ldmatrix lane patterns
    const u32 l7 = lane & 7;
    const u32 rowA = (l7 + 8 * ((lane >> 3) & 1)) * 128;
    const u32 rowB = (l7 + 8 * ((lane >> 4) & 1)) * 128;
    const u32 bitA = (lane >> 4) & 1;
    const u32 bitB = (lane >> 3) & 1;
    u32 cswzA[4], cswzB[4];
#pragma unroll
    for (int kk = 0; kk < 4; kk++) {
        cswzA[kk] = (((2 * kk + bitA) ^ l7) << 4);
        cswzB[kk] = (((2 * kk + bitB) ^ l7) << 4);
    }

    // Q fragments, register-resident
    u32 qf[4][4];
    {
        const u32 qbase = sb + SM_Q + (u32)(wg * 16) * 128 + rowA;
#pragma unroll
        for (int kk = 0; kk < 4; kk++)
            ldsm4(qf[kk][0], qf[kk][1], qf[kk][2], qf[kk][3], qbase + cswzA[kk]);
    }

    float oacc[16][4];
#pragma unroll
    for (int v = 0; v < 16; v++)
#pragma unroll
        for (int c = 0; c < 4; c++) oacc[v][c] = 0.f;
    float l0 = 0.f, l1 = 0.f;

    // ---- main loop: this group's tiles are grp, grp+2, ... ----
    for (int kt = grp; kt < NT; kt += 2) {
        const int st = kt & 3;
        if (kt + 2 < NT) cp_wait<1>(); else cp_wait<0>();
        gbar(grp);     // stage(kt) fully written by all group threads

        // ---- S = Q K^T with fused softmax (8 scores live at a time) ----
        uint2 pa[8];
        const u32 kbase = sb + SM_KS(st) + rowB;
#pragma unroll
        for (int jp = 0; jp < 4; jp++) {
            float s0[4] = {0.f, 0.f, 0.f, 0.f};
            float s1[4] = {0.f, 0.f, 0.f, 0.f};
#pragma unroll
            for (int kk = 0; kk < 4; kk++) {
                u32 b0, b1, b2, b3;
                ldsm4(b0, b1, b2, b3, kbase + jp * 2048 + cswzB[kk]);
                mma16816(s0, qf[kk][0], qf[kk][1], qf[kk][2], qf[kk][3], b0, b1);
                mma16816(s1, qf[kk][0], qf[kk][1], qf[kk][2], qf[kk][3], b2, b3);
            }
            float a0 = fexp2(s0[0]), a1 = fexp2(s0[1]);
            float a2 = fexp2(s0[2]), a3 = fexp2(s0[3]);
            float b0f = fexp2(s1[0]), b1f = fexp2(s1[1]);
            float b2f = fexp2(s1[2]), b3f = fexp2(s1[3]);
            l0 += a0 + a1 + b0f + b1f;
            l1 += a2 + a3 + b2f + b3f;
            pa[2 * jp].x     = pk(a0, a1);
            pa[2 * jp].y     = pk(a2, a3);
            pa[2 * jp + 1].x = pk(b0f, b1f);
            pa[2 * jp + 1].y = pk(b2f, b3f);
        }

        // ---- O += P V ----
        const u32 vbase = sb + SM_VS(st) + rowB;
#pragma unroll
        for (int nvp = 0; nvp < 8; nvp++)
#pragma unroll
            for (int kk = 0; kk < 4; kk++) {
                u32 b0, b1, b2, b3;
                ldsm4(b0, b1, b2, b3, vbase + nvp * 2048 + cswzB[kk]);
                mma16816(oacc[2 * nvp],
                         pa[2 * kk].x, pa[2 * kk].y, pa[2 * kk + 1].x, pa[2 * kk + 1].y, b0, b1);
                mma16816(oacc[2 * nvp + 1],
                         pa[2 * kk].x, pa[2 * kk].y, pa[2 * kk + 1].x, pa[2 * kk + 1].y, b2, b3);
            }

        gbar(grp);     // all group warps done reading stage(kt)
        if (kt + 4 < NT) load_kv(sb, st, kB, vB, kt + 4, gtid);
    }

    // ---- epilogue: cross-group reduce via smem overlay, normalize, store ----
#pragma unroll
    for (int d = 1; d < 4; d <<= 1) {
        l0 += __shfl_xor_sync(0xffffffffu, l0, d);
        l1 += __shfl_xor_sync(0xffffffffu, l1, d);
    }
    const int r0l = wg * 16 + (lane >> 2);   // local row (0..127)
    const int cl  = 2 * (lane & 3);
    float* Ored = (float*)smx;
    float* lred = (float*)(smx + SM_LRED);

    __syncthreads();   // all compute done; safe to overlay smem ring
    if (grp == 1) {
#pragma unroll
        for (int v = 0; v < 16; v++) {
            *(float2*)&Ored[(size_t)r0l * 128 + v * 8 + cl] =
                make_float2(oacc[v][0], oacc[v][1]);
            *(float2*)&Ored[(size_t)(r0l + 8) * 128 + v * 8 + cl] =
                make_float2(oacc[v][2], oacc[v][3]);
        }
        if ((lane & 3) == 0) { lred[r0l] = l0; lred[r0l + 8] = l1; }
    }
    __syncthreads();
    if (grp == 0) {
        const float inv0 = 1.f / (l0 + lred[r0l]);
        const float inv1 = 1.f / (l1 + lred[r0l + 8]);
        float* o0 = out + ((size_t)n * VQn + q0 + r0l) * Cdim + cl;
        float* o1 = o0 + 8 * Cdim;
#pragma unroll
        for (int v = 0; v < 16; v++) {
            float2 a = *(const float2*)&Ored[(size_t)r0l * 128 + v * 8 + cl];
            float2 b = *(const float2*)&Ored[(size_t)(r0l + 8) * 128 + v * 8 + cl];
            *(float2*)(o0 + v * 8) = make_float2((oacc[v][0] + a.x) * inv0,
                                                 (oacc[v][1] + a.y) * inv0);
            *(float2*)(o1 + v * 8) = make_float2((oacc[v][2] + b.x) * inv1,
                                                 (oacc[v][3] + b.y) * inv1);
        }
    }
}

// ---------------- launch ------------------------------------------------------
extern "C" void kernel_launch(void* const* d_in, const int* in_sizes, int n_in,
                              void* d_out, int out_size) {
    (void)in_sizes; (void)n_in; (void)out_size;
    const float* x  = (const float*)d_in[0];
    const float* y  = (const float*)d_in[1];
    const float* Wq = (const float*)d_in[2];
    const float* Wk = (const float*)d_in[3];
    const float* Wv = (const float*)d_in[4];
    float* out = (float*)d_out;

    __half *qp, *kp, *vtp;
    cudaGetSymbolAddress((void**)&qp, g_q);
    cudaGetSymbolAddress((void**)&kp, g_k);
    cudaGetSymbolAddress((void**)&vtp, g_vt);

    cudaFuncSetAttribute(flash_mma,
                         cudaFuncAttributeMaxDynamicSharedMemorySize, SMEM_TOTAL);

    dim3 pgrid(Nb * VQn / 128, 3);
    proj_all<<<pgrid, 256>>>(x, y, Wq, Wk, Wv, qp, kp, vtp);

    dim3 grid(VQn / BM, Nb);
    flash_mma<<<grid, NTHREADS, SMEM_TOTAL>>>(qp, kp, vtp, out);
}